// round 12
// baseline (speedup 1.0000x reference)
#include <cuda_runtime.h>
#include <cuda_fp16.h>
#include <cstdint>
#include <cstddef>

// ---------------------------------------------------------------------------
// SparseLinear on GB300 (bare sm_103 ptxas target -> no tcgen05).
// mma.sync.m16n8k16 (HMMA) pipeline; dense GEMM == reference math since
// masked channels are exactly zero in X.
// fp16 inputs, fp32 accumulate: measured rel_err 2.9e-4 < 1e-3 gate.
//
// R12: CTA tile widened 128x128 -> 256(M)x128(N), 16 warps (512 thr),
// warp grid 8Mx2N, warp tile 32x64 BYTE-IDENTICAL audited datapath.
// Cuts smem fill 25% (8.6 -> 6.4 GB) to relieve the shared smem port
// (LDSM reads + cp.async writes ~900us floor vs HMMA ~900us floor).
// NSTAGE=4 x 24KB = 96KB; launch_bounds(512,1): reg cap 128 (~105 used),
// 16 warps/SM (same as previous 2x8).
// ---------------------------------------------------------------------------

#define NROWS 16384
#define CIN   4096
#define COUT  4096

#define TM 256                     // x rows per CTA (MMA M)
#define TN 128                     // output channels per CTA (MMA N)
#define KSTEP 32
#define NSTAGE 4
#define NKS (CIN / KSTEP)          // 128

#define SLOT_A 0
#define SLOT_B (TM * KSTEP * 2)    // 16384
#define SLOT_BYTES (SLOT_B + TN * KSTEP * 2)   // 24576
#define SMEM_TOTAL (NSTAGE * SLOT_BYTES)       // 98304

// ------------------------- scratch (device globals) ------------------------
__device__ __align__(256) __half g_w_h[(size_t)COUT * CIN];
__device__ __align__(256) __half g_x_h[(size_t)NROWS * CIN];

// ------------------------------- helpers -----------------------------------
static __device__ __forceinline__ uint32_t smem_u32(const void* p) {
    uint32_t a;
    asm("{ .reg .u64 t; cvta.to.shared.u64 t, %1; cvt.u32.u64 %0, t; }"
        : "=r"(a) : "l"(p));
    return a;
}

static __device__ __forceinline__ void cp16(uint32_t dst, const void* src) {
    asm volatile("cp.async.cg.shared.global [%0], [%1], 16;"
                 :: "r"(dst), "l"(src));
}

// smem byte offset of 16B chunk (row, chunk): 64B rows, XOR swizzle so the
// 8-row ldmatrix phases hit 8 distinct 16B granules mod 128B (conflict-free,
// also for the cp.async store phases).
static __device__ __forceinline__ uint32_t sw(int row, int chunk) {
    return (uint32_t)(row * 64 + ((chunk ^ ((row >> 1) & 3)) << 4));
}

static __device__ __forceinline__ void ldsm4(uint32_t& r0, uint32_t& r1,
                                             uint32_t& r2, uint32_t& r3,
                                             uint32_t addr) {
    asm volatile("ldmatrix.sync.aligned.m8n8.x4.shared.b16 {%0,%1,%2,%3}, [%4];"
                 : "=r"(r0), "=r"(r1), "=r"(r2), "=r"(r3) : "r"(addr));
}

static __device__ __forceinline__ void mma16816(float* c, const uint32_t* a,
                                                uint32_t b0, uint32_t b1) {
    asm volatile(
        "mma.sync.aligned.m16n8k16.row.col.f32.f16.f16.f32 "
        "{%0,%1,%2,%3}, {%4,%5,%6,%7}, {%8,%9}, {%0,%1,%2,%3};"
        : "+f"(c[0]), "+f"(c[1]), "+f"(c[2]), "+f"(c[3])
        : "r"(a[0]), "r"(a[1]), "r"(a[2]), "r"(a[3]), "r"(b0), "r"(b1));
}

static __device__ __forceinline__ void stg2cs(float* p, float v0, float v1) {
    asm volatile("st.global.cs.v2.f32 [%0], {%1,%2};"
                 :: "l"(p), "f"(v0), "f"(v1) : "memory");
}

// 3 cp.asyncs per thread per stage (512 threads): A(2) + B(1), 16B each.
static __device__ __forceinline__ void load_stage(uint32_t slot, int rb,
                                                  int o0, int c0, int tid) {
    #pragma unroll
    for (int i = 0; i < 2; ++i) {
        int c = tid + i * 512;          // chunk id 0..1023
        int row = c >> 2, j = c & 3;    // x row 0..255, 16B chunk 0..3
        cp16(slot + SLOT_A + sw(row, j),
             g_x_h + (size_t)(rb + row) * CIN + c0 + j * 8);
    }
    {
        int c = tid;                    // chunk id 0..511
        int row = c >> 2, j = c & 3;    // W row 0..127
        cp16(slot + SLOT_B + sw(row, j),
             g_w_h + (size_t)(o0 + row) * CIN + c0 + j * 8);
    }
}

// --------------------------- conversion kernels ----------------------------
__global__ void conv_w_kernel(const float* __restrict__ w) {
    size_t i = ((size_t)blockIdx.x * blockDim.x + threadIdx.x) * 4;
    float4 v = __ldcs(reinterpret_cast<const float4*>(w + i));
    __half2* h2 = reinterpret_cast<__half2*>(g_w_h + i);
    h2[0] = __halves2half2(__float2half(v.x), __float2half(v.y));
    h2[1] = __halves2half2(__float2half(v.z), __float2half(v.w));
}

__global__ void conv_x_kernel(const float* __restrict__ x) {
    size_t i = ((size_t)blockIdx.x * blockDim.x + threadIdx.x) * 4;
    float4 v = __ldcs(reinterpret_cast<const float4*>(x + i));
    __half2* h2 = reinterpret_cast<__half2*>(g_x_h + i);
    h2[0] = __halves2half2(__float2half(v.x), __float2half(v.y));
    h2[1] = __halves2half2(__float2half(v.z), __float2half(v.w));
}

// ------------------------------ GEMM kernel --------------------------------
__global__ __launch_bounds__(512, 1)
void gemm_kernel(const float* __restrict__ bias, float* __restrict__ out) {
    extern __shared__ char smem[];
    const uint32_t sb = smem_u32(smem);
    const int tid = threadIdx.x;
    const int lane = tid & 31, wid = tid >> 5;   // wid 0..15
    const int o0 = blockIdx.x * TN;     // output-channel tile
    const int rb = blockIdx.y * TM;     // x-row tile
    const int wm = (wid & 7) * 32;      // warp M offset (8 M-warps)
    const int wn = (wid >> 3) * 64;     // warp N offset (2 N-warps)

    float acc[2][8][4];
    #pragma unroll
    for (int mt = 0; mt < 2; ++mt)
        #pragma unroll
        for (int nt = 0; nt < 8; ++nt)
            #pragma unroll
            for (int q = 0; q < 4; ++q) acc[mt][nt][q] = 0.0f;

    // prologue: fill NSTAGE-1 stages
    #pragma unroll
    for (int s = 0; s < NSTAGE - 1; ++s) {
        load_stage(sb + s * SLOT_BYTES, rb, o0, s * KSTEP, tid);
        asm volatile("cp.async.commit_group;");
    }

    for (int ks = 0; ks < NKS; ++ks) {
        asm volatile("cp.async.wait_group %0;" :: "n"(NSTAGE - 2));
        __syncthreads();

        // prefetch stage ks+NSTAGE-1 into slot (ks-1)%NSTAGE
        // (that slot's reads finished before this iteration's __syncthreads)
        const int ns = ks + NSTAGE - 1;
        if (ns < NKS)
            load_stage(sb + (ns % NSTAGE) * SLOT_BYTES, rb, o0,
                       ns * KSTEP, tid);
        asm volatile("cp.async.commit_group;");

        const uint32_t slot = sb + (ks % NSTAGE) * SLOT_BYTES;
        #pragma unroll
        for (int kk = 0; kk < 2; ++kk) {           // two k16 halves of K32
            const int jb = kk * 2;
            uint32_t a[2][4];
            #pragma unroll
            for (int mt = 0; mt < 2; ++mt) {
                int row = wm + mt * 16 + (lane & 15);
                int ch = jb + (lane >> 4);
                ldsm4(a[mt][0], a[mt][1], a[mt][2], a[mt][3],
                      slot + SLOT_A + sw(row, ch));
            }
            #pragma unroll
            for (int np = 0; np < 4; ++np) {       // 2 n8-tiles per ldmatrix
                int row = wn + np * 16 + (lane & 7) + ((lane >> 4) << 3);
                int ch = jb + ((lane >> 3) & 1);
                uint32_t b0, b1, b2, b3;
                ldsm4(b0, b1, b2, b3, slot + SLOT_B + sw(row, ch));
                #pragma unroll
                for (int mt = 0; mt < 2; ++mt) {
                    mma16816(acc[mt][2 * np],     a[mt], b0, b1);
                    mma16816(acc[mt][2 * np + 1], a[mt], b2, b3);
                }
            }
        }
    }

    // epilogue: c frag (r=lane/4, c=2*(lane%4)); float2 stores, evict-first
    #pragma unroll
    for (int nt = 0; nt < 8; ++nt) {
        const int c = o0 + wn + nt * 8 + 2 * (lane & 3);
        const float bc0 = __ldg(bias + c), bc1 = __ldg(bias + c + 1);
        #pragma unroll
        for (int mt = 0; mt < 2; ++mt) {
            const int r = rb + wm + mt * 16 + (lane >> 2);
            stg2cs(out + (size_t)r * COUT + c,
                   acc[mt][nt][0] + bc0, acc[mt][nt][1] + bc1);
            stg2cs(out + (size_t)(r + 8) * COUT + c,
                   acc[mt][nt][2] + bc0, acc[mt][nt][3] + bc1);
        }
    }
}

// ------------------------------ launch -------------------------------------
extern "C" void kernel_launch(void* const* d_in, const int* in_sizes, int n_in,
                              void* d_out, int out_size) {
    const float* x    = (const float*)d_in[0];
    const float* w    = (const float*)d_in[1];
    const float* bias = (const float*)d_in[2];
    float* out = (float*)d_out;
    (void)in_sizes; (void)n_in; (void)out_size;

    cudaFuncSetAttribute(gemm_kernel,
                         cudaFuncAttributeMaxDynamicSharedMemorySize, SMEM_TOTAL);

    conv_w_kernel<<<(size_t)COUT * CIN / 4 / 256, 256>>>(w);
    conv_x_kernel<<<(size_t)NROWS * CIN / 4 / 256, 256>>>(x);

    dim3 grid(COUT / TN, NROWS / TM);   // (32, 64)
    gemm_kernel<<<grid, 512, SMEM_TOTAL>>>(bias, out);
}

// round 13
// speedup vs baseline: 1.1407x; 1.1407x over previous
#include <cuda_runtime.h>
#include <cuda_fp16.h>
#include <cstdint>
#include <cstddef>

// ---------------------------------------------------------------------------
// SparseLinear on GB300 (bare sm_103 ptxas target -> no tcgen05).
// mma.sync.m16n8k16 (HMMA) pipeline; dense GEMM == reference math since
// masked channels are exactly zero in X.
// fp16 inputs, fp32 accumulate: measured rel_err 2.9e-4 < 1e-3 gate.
//
// R13: revert to R11 shape (CTA 128x128, 256 thr, 2 CTA/SM; R12's 512-thr
// single-CTA config regressed 1378->1561 by coupling 16 warps on one
// barrier). Change: KSTEP 32->64 as two 32-K slabs per stage, each slab
// byte-identical to the audited 64B-row layout. Halves barrier count and
// doubles the dependency-free compute run per barrier (overlap deficit
// ~400us vs the ~900us HMMA / smem-port floors). NSTAGE=3 x 32KB: in-flight
// lead 64KB, same as R11. Conversions merged into one launch.
// ---------------------------------------------------------------------------

#define NROWS 16384
#define CIN   4096
#define COUT  4096

#define TM 128
#define TN 128
#define KSTEP 64
#define NSTAGE 3
#define NKS (CIN / KSTEP)          // 64

#define SLAB 8192                  // one 32-K slab: 128 rows x 64 B
#define SLOT_A 0
#define SLOT_B (2 * SLAB)          // 16384
#define SLOT_BYTES (4 * SLAB)      // 32768
#define SMEM_TOTAL (NSTAGE * SLOT_BYTES)   // 98304

// ------------------------- scratch (device globals) ------------------------
__device__ __align__(256) __half g_w_h[(size_t)COUT * CIN];
__device__ __align__(256) __half g_x_h[(size_t)NROWS * CIN];

// ------------------------------- helpers -----------------------------------
static __device__ __forceinline__ uint32_t smem_u32(const void* p) {
    uint32_t a;
    asm("{ .reg .u64 t; cvta.to.shared.u64 t, %1; cvt.u32.u64 %0, t; }"
        : "=r"(a) : "l"(p));
    return a;
}

static __device__ __forceinline__ void cp16(uint32_t dst, const void* src) {
    asm volatile("cp.async.cg.shared.global [%0], [%1], 16;"
                 :: "r"(dst), "l"(src));
}

// smem byte offset of 16B chunk (row, chunk) within one slab: 64B rows, XOR
// swizzle so 8-row ldmatrix phases hit 8 distinct granules mod 128B
// (conflict-free for loads and the cp.async store phases).
static __device__ __forceinline__ uint32_t sw(int row, int chunk) {
    return (uint32_t)(row * 64 + ((chunk ^ ((row >> 1) & 3)) << 4));
}

static __device__ __forceinline__ void ldsm4(uint32_t& r0, uint32_t& r1,
                                             uint32_t& r2, uint32_t& r3,
                                             uint32_t addr) {
    asm volatile("ldmatrix.sync.aligned.m8n8.x4.shared.b16 {%0,%1,%2,%3}, [%4];"
                 : "=r"(r0), "=r"(r1), "=r"(r2), "=r"(r3) : "r"(addr));
}

static __device__ __forceinline__ void mma16816(float* c, const uint32_t* a,
                                                uint32_t b0, uint32_t b1) {
    asm volatile(
        "mma.sync.aligned.m16n8k16.row.col.f32.f16.f16.f32 "
        "{%0,%1,%2,%3}, {%4,%5,%6,%7}, {%8,%9}, {%0,%1,%2,%3};"
        : "+f"(c[0]), "+f"(c[1]), "+f"(c[2]), "+f"(c[3])
        : "r"(a[0]), "r"(a[1]), "r"(a[2]), "r"(a[3]), "r"(b0), "r"(b1));
}

static __device__ __forceinline__ void stg2cs(float* p, float v0, float v1) {
    asm volatile("st.global.cs.v2.f32 [%0], {%1,%2};"
                 :: "l"(p), "f"(v0), "f"(v1) : "memory");
}

// 8 cp.asyncs per thread per stage (256 threads): per slab A(2) + B(2).
static __device__ __forceinline__ void load_stage(uint32_t slot, int rb,
                                                  int o0, int c0, int tid) {
    #pragma unroll
    for (int s2 = 0; s2 < 2; ++s2) {
        const int cbase = c0 + s2 * 32;
        const uint32_t sa = slot + SLOT_A + s2 * SLAB;
        const uint32_t sbb = slot + SLOT_B + s2 * SLAB;
        #pragma unroll
        for (int i = 0; i < 2; ++i) {
            int c = tid + i * 256;          // chunk id 0..511
            int row = c >> 2, j = c & 3;    // row 0..127, 16B chunk 0..3
            cp16(sa + sw(row, j),
                 g_x_h + (size_t)(rb + row) * CIN + cbase + j * 8);
            cp16(sbb + sw(row, j),
                 g_w_h + (size_t)(o0 + row) * CIN + cbase + j * 8);
        }
    }
}

// --------------------------- conversion kernel (merged) --------------------
#define W_VEC4 ((size_t)COUT * CIN / 4)     // 4,194,304
#define X_VEC4 ((size_t)NROWS * CIN / 4)    // 16,777,216

__global__ void conv_wx_kernel(const float* __restrict__ w,
                               const float* __restrict__ x) {
    size_t g = (size_t)blockIdx.x * blockDim.x + threadIdx.x;
    const float* src;
    __half2* dst;
    if (g < W_VEC4) {
        src = w + g * 4;
        dst = reinterpret_cast<__half2*>(g_w_h + g * 4);
    } else {
        size_t gx = g - W_VEC4;
        src = x + gx * 4;
        dst = reinterpret_cast<__half2*>(g_x_h + gx * 4);
    }
    float4 v = __ldcs(reinterpret_cast<const float4*>(src));
    dst[0] = __halves2half2(__float2half(v.x), __float2half(v.y));
    dst[1] = __halves2half2(__float2half(v.z), __float2half(v.w));
}

// ------------------------------ GEMM kernel --------------------------------
__global__ __launch_bounds__(256, 2)
void gemm_kernel(const float* __restrict__ bias, float* __restrict__ out) {
    extern __shared__ char smem[];
    const uint32_t sb = smem_u32(smem);
    const int tid = threadIdx.x;
    const int lane = tid & 31, wid = tid >> 5;
    const int o0 = blockIdx.x * TN;     // output-channel tile
    const int rb = blockIdx.y * TM;     // x-row tile
    const int wm = (wid & 3) * 32;      // warp M offset
    const int wn = (wid >> 2) * 64;     // warp N offset

    float acc[2][8][4];
    #pragma unroll
    for (int mt = 0; mt < 2; ++mt)
        #pragma unroll
        for (int nt = 0; nt < 8; ++nt)
            #pragma unroll
            for (int q = 0; q < 4; ++q) acc[mt][nt][q] = 0.0f;

    // prologue: fill NSTAGE-1 stages
    #pragma unroll
    for (int s = 0; s < NSTAGE - 1; ++s) {
        load_stage(sb + s * SLOT_BYTES, rb, o0, s * KSTEP, tid);
        asm volatile("cp.async.commit_group;");
    }

    for (int ks = 0; ks < NKS; ++ks) {
        asm volatile("cp.async.wait_group %0;" :: "n"(NSTAGE - 2));
        __syncthreads();

        // prefetch stage ks+NSTAGE-1 into slot (ks-1)%NSTAGE
        // (that slot's reads finished before this iteration's __syncthreads)
        const int ns = ks + NSTAGE - 1;
        if (ns < NKS)
            load_stage(sb + (ns % NSTAGE) * SLOT_BYTES, rb, o0,
                       ns * KSTEP, tid);
        asm volatile("cp.async.commit_group;");

        const uint32_t slot = sb + (ks % NSTAGE) * SLOT_BYTES;
        #pragma unroll
        for (int s2 = 0; s2 < 2; ++s2) {           // two 32-K slabs
            const uint32_t sa = slot + SLOT_A + s2 * SLAB;
            const uint32_t sbb = slot + SLOT_B + s2 * SLAB;
            #pragma unroll
            for (int kk = 0; kk < 2; ++kk) {       // two k16 halves per slab
                const int jb = kk * 2;
                uint32_t a[2][4];
                #pragma unroll
                for (int mt = 0; mt < 2; ++mt) {
                    int row = wm + mt * 16 + (lane & 15);
                    int ch = jb + (lane >> 4);
                    ldsm4(a[mt][0], a[mt][1], a[mt][2], a[mt][3],
                          sa + sw(row, ch));
                }
                #pragma unroll
                for (int np = 0; np < 4; ++np) {   // 2 n8-tiles per ldmatrix
                    int row = wn + np * 16 + (lane & 7) + ((lane >> 4) << 3);
                    int ch = jb + ((lane >> 3) & 1);
                    uint32_t b0, b1, b2, b3;
                    ldsm4(b0, b1, b2, b3, sbb + sw(row, ch));
                    #pragma unroll
                    for (int mt = 0; mt < 2; ++mt) {
                        mma16816(acc[mt][2 * np],     a[mt], b0, b1);
                        mma16816(acc[mt][2 * np + 1], a[mt], b2, b3);
                    }
                }
            }
        }
    }

    // epilogue: c frag (r=lane/4, c=2*(lane%4)); float2 stores, evict-first
    #pragma unroll
    for (int nt = 0; nt < 8; ++nt) {
        const int c = o0 + wn + nt * 8 + 2 * (lane & 3);
        const float bc0 = __ldg(bias + c), bc1 = __ldg(bias + c + 1);
        #pragma unroll
        for (int mt = 0; mt < 2; ++mt) {
            const int r = rb + wm + mt * 16 + (lane >> 2);
            stg2cs(out + (size_t)r * COUT + c,
                   acc[mt][nt][0] + bc0, acc[mt][nt][1] + bc1);
            stg2cs(out + (size_t)(r + 8) * COUT + c,
                   acc[mt][nt][2] + bc0, acc[mt][nt][3] + bc1);
        }
    }
}

// ------------------------------ launch -------------------------------------
extern "C" void kernel_launch(void* const* d_in, const int* in_sizes, int n_in,
                              void* d_out, int out_size) {
    const float* x    = (const float*)d_in[0];
    const float* w    = (const float*)d_in[1];
    const float* bias = (const float*)d_in[2];
    float* out = (float*)d_out;
    (void)in_sizes; (void)n_in; (void)out_size;

    cudaFuncSetAttribute(gemm_kernel,
                         cudaFuncAttributeMaxDynamicSharedMemorySize, SMEM_TOTAL);

    conv_wx_kernel<<<(unsigned)((W_VEC4 + X_VEC4) / 256), 256>>>(w, x);

    dim3 grid(COUT / TN, NROWS / TM);   // (32, 128)
    gemm_kernel<<<grid, 256, SMEM_TOTAL>>>(bias, out);
}